// round 7
// baseline (speedup 1.0000x reference)
#include <cuda_runtime.h>
#include <cstdint>

// RegressionLoss: masked SmoothL1 (beta=0.5) sum over N=16,777,216 elements.
//   d = outs - labels; ad = |d|
//   sl1 = ad < 0.5 ? d*d : ad - 0.25       (beta=0.5: 0.5*d*d/0.5 = d*d)
//   keep if ad >= 1/len
//   out[0] = sum(keep ? sl1 : 0)
//
// NOTE: reference declares lens as jnp.int64, but JAX without x64 downcasts
// to int32 — the device buffer is int32 (int64 reads crashed OOB in R4).
// Read as int4.
//
// HBM-bound: 192 MiB of reads -> roofline ~30 us.

__global__ void zero_out_kernel(float* __restrict__ out) {
    if (threadIdx.x == 0) out[0] = 0.0f;
}

__device__ __forceinline__ float sl1_masked(float o, float l, float lenf) {
    float d  = o - l;
    float ad = fabsf(d);
    float v  = (ad < 0.5f) ? (d * d) : (ad - 0.25f);
    // mask: ad >= 1/len  <=>  ad*len >= 1 (len in [1,1000]; edge noise ~1ulp)
    return (ad * lenf >= 1.0f) ? v : 0.0f;
}

__global__ __launch_bounds__(256, 8)
void smoothl1_masked_sum_kernel(const float4* __restrict__ outs4,
                                const float4* __restrict__ labels4,
                                const int4*   __restrict__ lens4,
                                const float*  __restrict__ outs,
                                const float*  __restrict__ labels,
                                const int*    __restrict__ lens,
                                float* __restrict__ out,
                                int nvec, int n) {
    float acc = 0.0f;
    const int stride = gridDim.x * blockDim.x;
    int i = blockIdx.x * blockDim.x + threadIdx.x;

    for (; i < nvec; i += stride) {
        float4 o = outs4[i];
        float4 l = labels4[i];
        int4   L = lens4[i];
        acc += sl1_masked(o.x, l.x, (float)L.x);
        acc += sl1_masked(o.y, l.y, (float)L.y);
        acc += sl1_masked(o.z, l.z, (float)L.z);
        acc += sl1_masked(o.w, l.w, (float)L.w);
    }

    // scalar tail (n not divisible by 4)
    int t = nvec * 4 + blockIdx.x * blockDim.x + threadIdx.x;
    if (t < n) {
        acc += sl1_masked(outs[t], labels[t], (float)lens[t]);
    }

    // warp reduce
    #pragma unroll
    for (int off = 16; off > 0; off >>= 1)
        acc += __shfl_xor_sync(0xffffffffu, acc, off);

    __shared__ float warp_sums[8];
    int lane = threadIdx.x & 31;
    int wid  = threadIdx.x >> 5;
    if (lane == 0) warp_sums[wid] = acc;
    __syncthreads();

    if (wid == 0) {
        float v = (lane < 8) ? warp_sums[lane] : 0.0f;
        #pragma unroll
        for (int off = 4; off > 0; off >>= 1)
            v += __shfl_xor_sync(0xffffffffu, v, off);
        if (lane == 0) atomicAdd(out, v);
    }
}

extern "C" void kernel_launch(void* const* d_in, const int* in_sizes, int n_in,
                              void* d_out, int out_size) {
    const float* outs   = (const float*)d_in[0];
    const float* labels = (const float*)d_in[1];
    const int*   lens   = (const int*)d_in[2];   // int32 on device (JAX x64 off)
    float* out = (float*)d_out;
    const int n    = in_sizes[0];
    const int nvec = n >> 2;

    zero_out_kernel<<<1, 32>>>(out);

    const int threads = 256;
    int blocks = 148 * 16;   // ~606k threads, ~7 float4 iters each
    int max_blocks = (nvec + threads - 1) / threads;
    if (blocks > max_blocks && max_blocks > 0) blocks = max_blocks;
    if (blocks < 1) blocks = 1;

    smoothl1_masked_sum_kernel<<<blocks, threads>>>(
        (const float4*)outs, (const float4*)labels, (const int4*)lens,
        outs, labels, lens, out, nvec, n);
}